// round 1
// baseline (speedup 1.0000x reference)
#include <cuda_runtime.h>
#include <math.h>

// ---- problem constants ----
#define Bb   4
#define Nn   2048
#define Dd   512
#define Ee   8
#define Hh   1365
#define H2   2730
#define CAP  320
#define NTOK (Bb*Nn)           // 8192
#define NSLOT (Bb*Ee*CAP)      // 10240
#define BND  (Bb*Nn*Dd)        // 4194304

// ---- scratch (static device arrays; no allocation allowed) ----
__device__ float d_xg[BND];                 // rmsnormed tokens
__device__ float d_ein[NSLOT*Dd];           // gathered expert input  (zeros for empty slots)
__device__ float d_act[NSLOT*Hh];           // GEGLU activations
__device__ float d_eo[NSLOT*Dd];            // expert outputs
__device__ int   d_e0[NTOK], d_e1[NTOK], d_r1[NTOK];
__device__ float d_g0[NTOK], d_g1[NTOK];
__device__ int   d_s0[NTOK], d_s1[NTOK];    // assigned global slot (-1 if dropped)
__device__ int   d_slot_tok[NSLOT];         // token n within batch, -1 if empty
__device__ float d_gsum[Bb*Ee];             // sum of raw softmax gates per (b,e)
__device__ int   d_c0cnt[Bb*Ee];            // kept count for k=0 (density_1 numerator)
__device__ float d_zsum;                    // sum of logsumexp^2

// =====================  JAX threefry (partitionable path) ======================
__device__ __forceinline__ unsigned rotl32(unsigned x, int d) {
    return (x << d) | (x >> (32 - d));
}

// jax.random.uniform(key(42), ...) with threefry_partitionable=True:
// bits[i] = x0 ^ x1 of threefry2x32(key=(0,42), counts=(hi(i)=0, lo(i)=i))
__device__ float jax_uniform_idx(unsigned idx) {
    const unsigned k0 = 0u, k1 = 42u;
    const unsigned k2 = k0 ^ k1 ^ 0x1BD11BDAu;
    unsigned x0 = 0u + k0;     // counts_hi + ks[0]
    unsigned x1 = idx + k1;    // counts_lo + ks[1]
#define TF_RND(r) { x0 += x1; x1 = rotl32(x1, r); x1 ^= x0; }
    TF_RND(13) TF_RND(15) TF_RND(26) TF_RND(6)   x0 += k1; x1 += k2 + 1u;
    TF_RND(17) TF_RND(29) TF_RND(16) TF_RND(24)  x0 += k2; x1 += k0 + 2u;
    TF_RND(13) TF_RND(15) TF_RND(26) TF_RND(6)   x0 += k0; x1 += k1 + 3u;
    TF_RND(17) TF_RND(29) TF_RND(16) TF_RND(24)  x0 += k1; x1 += k2 + 4u;
    TF_RND(13) TF_RND(15) TF_RND(26) TF_RND(6)   x0 += k2; x1 += k0 + 5u;
#undef TF_RND
    unsigned bits = x0 ^ x1;
    return __uint_as_float((bits >> 9) | 0x3f800000u) - 1.0f;
}

// =====================  init  ======================
__global__ void init_kernel() {
    int i = blockIdx.x * blockDim.x + threadIdx.x;
    if (i < NSLOT) d_slot_tok[i] = -1;
    if (i < Bb*Ee) d_gsum[i] = 0.f;
    if (i == 0)    d_zsum = 0.f;
}

// =====================  per-token: rmsnorm + router  ======================
__global__ void token_kernel(const float* __restrict__ x,
                             const float* __restrict__ gw,
                             const float* __restrict__ pg) {
    int t = blockIdx.x;
    int tid = threadIdx.x;          // 128 threads
    int b = t / Nn;
    const float* xr = x + (size_t)t * Dd;

    float xv[4];
    float ss = 0.f;
#pragma unroll
    for (int i = 0; i < 4; i++) {
        float v = xr[tid + i*128];
        xv[i] = v;
        ss += v * v;
    }
    __shared__ float s_red[128];
    s_red[tid] = ss;
    __syncthreads();
    for (int s = 64; s > 0; s >>= 1) {
        if (tid < s) s_red[tid] += s_red[tid + s];
        __syncthreads();
    }
    float nrm = fmaxf(sqrtf(s_red[0]), 1e-12f);
    float scale = 22.627416997969520780827019587355f / nrm; // sqrt(512)

    float p[Ee];
#pragma unroll
    for (int e = 0; e < Ee; e++) p[e] = 0.f;
#pragma unroll
    for (int i = 0; i < 4; i++) {
        int d = tid + i*128;
        float v = xv[i] * scale * pg[d];
        d_xg[(size_t)t * Dd + d] = v;
#pragma unroll
        for (int e = 0; e < Ee; e++) p[e] += v * gw[d*Ee + e];
    }
    __shared__ float s_l[Ee][128];
#pragma unroll
    for (int e = 0; e < Ee; e++) s_l[e][tid] = p[e];
    __syncthreads();
    for (int s = 64; s > 0; s >>= 1) {
        if (tid < s)
#pragma unroll
            for (int e = 0; e < Ee; e++) s_l[e][tid] += s_l[e][tid + s];
        __syncthreads();
    }
    if (tid == 0) {
        float lg[Ee], mx = -1e30f;
#pragma unroll
        for (int e = 0; e < Ee; e++) { lg[e] = s_l[e][0]; mx = fmaxf(mx, lg[e]); }
        float se = 0.f, ge[Ee];
#pragma unroll
        for (int e = 0; e < Ee; e++) { ge[e] = expf(lg[e] - mx); se += ge[e]; }
#pragma unroll
        for (int e = 0; e < Ee; e++) ge[e] = ge[e] / se;
        // router z loss
        float z = mx + logf(se);
        atomicAdd(&d_zsum, z * z);
#pragma unroll
        for (int e = 0; e < Ee; e++) atomicAdd(&d_gsum[b*Ee + e], ge[e]);
        // top-2 (first occurrence wins ties, matching lax.top_k)
        float m1 = -1e30f, m2 = -1e30f; int i1 = 0, i2 = 0;
#pragma unroll
        for (int e = 0; e < Ee; e++) {
            float v = ge[e];
            if (v > m1)      { m2 = m1; i2 = i1; m1 = v; i1 = e; }
            else if (v > m2) { m2 = v;  i2 = e; }
        }
        float denom = fmaxf(m1 + m2, 1e-9f);
        float g0 = m1 / denom, g1 = m2 / denom;
        float prob = jax_uniform_idx(8192u + (unsigned)t);   // probs[1] plane
        int r1 = prob < (g1 / 0.2f);
        d_e0[t] = i1; d_e1[t] = i2;
        d_g0[t] = g0; d_g1[t] = g1;
        d_r1[t] = r1;
    }
}

// =====================  capacity scan (warp ballots, 1 warp per batch) ==========
__global__ void scan_kernel() {
    int b = blockIdx.x;
    int lane = threadIdx.x;
    unsigned ltmask = (1u << lane) - 1u;

    int cnt[Ee];
#pragma unroll
    for (int e = 0; e < Ee; e++) cnt[e] = 0;

    // ---- pass k=0 (always routed) ----
    for (int c = 0; c < Nn/32; c++) {
        int n = c*32 + lane;
        int t = b*Nn + n;
        int e = d_e0[t];
        int pos = 0;
#pragma unroll
        for (int ei = 0; ei < Ee; ei++) {
            unsigned bal = __ballot_sync(0xffffffffu, e == ei);
            if (e == ei) pos = cnt[ei] + __popc(bal & ltmask);
            cnt[ei] += __popc(bal);
        }
        if (pos < CAP) {
            int slot = (b*Ee + e)*CAP + pos;
            d_slot_tok[slot] = n;
            d_s0[t] = slot;
        } else {
            d_s0[t] = -1;
        }
    }
    int c0[Ee];
#pragma unroll
    for (int e = 0; e < Ee; e++) c0[e] = min(cnt[e], CAP);
    if (lane < Ee) d_c0cnt[b*Ee + lane] = c0[lane];

    // ---- pass k=1 (stochastic) ----
    int cnt1[Ee];
#pragma unroll
    for (int e = 0; e < Ee; e++) cnt1[e] = 0;
    for (int c = 0; c < Nn/32; c++) {
        int n = c*32 + lane;
        int t = b*Nn + n;
        int e = d_r1[t] ? d_e1[t] : -1;
        int posl = 0;
#pragma unroll
        for (int ei = 0; ei < Ee; ei++) {
            unsigned bal = __ballot_sync(0xffffffffu, e == ei);
            if (e == ei) posl = cnt1[ei] + __popc(bal & ltmask);
            cnt1[ei] += __popc(bal);
        }
        if (e >= 0) {
            int pos = c0[e] + posl;
            if (pos < CAP) {
                int slot = (b*Ee + e)*CAP + pos;
                d_slot_tok[slot] = n;
                d_s1[t] = slot;
            } else {
                d_s1[t] = -1;
            }
        } else {
            d_s1[t] = -1;
        }
    }
}

// =====================  gather xg rows into slot layout ======================
__global__ void gather_kernel() {
    int r = blockIdx.x;
    int tid = threadIdx.x;
    int tok = d_slot_tok[r];
    int b = r / (Ee*CAP);
#pragma unroll
    for (int i = 0; i < 4; i++) {
        int d = tid + i*128;
        d_ein[(size_t)r*Dd + d] =
            (tok >= 0) ? d_xg[((size_t)(b*Nn + tok))*Dd + d] : 0.f;
    }
}

// =====================  GEMM1: ein @ w1 -> GEGLU act ======================
// per-expert A(320x512) * W(512x2730); act[r,j] = (u+b1u)*gelu(g+b1g)*mb
__global__ void gemm1_kernel(const float* __restrict__ w1,
                             const float* __restrict__ b1,
                             const float* __restrict__ mb) {
    __shared__ float As[16][65];
    __shared__ float Bu[16][64];
    __shared__ float Bg[16][64];
    int g = blockIdx.z, e = g & 7;
    int rowbase = g*CAP + blockIdx.y*64;
    int j0 = blockIdx.x*64;
    int tid = threadIdx.x;
    int tx = tid & 15, ty = tid >> 4;
    float aU[4][4] = {}, aG[4][4] = {};
    const float* w1e = w1 + (size_t)e * Dd * H2;
    const float* b1e = b1 + e * H2;

    for (int k0 = 0; k0 < Dd; k0 += 16) {
        {   // A tile (float4, K is mult of 16)
            int m = tid >> 2, kq = (tid & 3)*4;
            float4 av = *reinterpret_cast<const float4*>(
                d_ein + (size_t)(rowbase + m)*Dd + k0 + kq);
            As[kq+0][m] = av.x; As[kq+1][m] = av.y;
            As[kq+2][m] = av.z; As[kq+3][m] = av.w;
        }
        {   // B tiles for u-cols and g-cols
            int kb = tid >> 4, jj = (tid & 15)*4;
            const float* bp = w1e + (size_t)(k0 + kb) * H2;
#pragma unroll
            for (int q = 0; q < 4; q++) {
                int jc = j0 + jj + q;
                float bu = 0.f, bg = 0.f;
                if (jc < Hh) { bu = bp[jc]; bg = bp[Hh + jc]; }
                Bu[kb][jj+q] = bu; Bg[kb][jj+q] = bg;
            }
        }
        __syncthreads();
#pragma unroll
        for (int k = 0; k < 16; k++) {
            float a[4], u[4], gg[4];
#pragma unroll
            for (int i = 0; i < 4; i++) a[i] = As[k][ty*4 + i];
#pragma unroll
            for (int j = 0; j < 4; j++) { u[j] = Bu[k][tx*4 + j]; gg[j] = Bg[k][tx*4 + j]; }
#pragma unroll
            for (int i = 0; i < 4; i++)
#pragma unroll
                for (int j = 0; j < 4; j++) {
                    aU[i][j] += a[i]*u[j];
                    aG[i][j] += a[i]*gg[j];
                }
        }
        __syncthreads();
    }
#pragma unroll
    for (int i = 0; i < 4; i++) {
        int r = rowbase + ty*4 + i;
#pragma unroll
        for (int j = 0; j < 4; j++) {
            int jc = j0 + tx*4 + j;
            if (jc < Hh) {
                float uu = aU[i][j] + b1e[jc];
                float gg = aG[i][j] + b1e[Hh + jc];
                float gel = 0.5f * gg * (1.f + erff(gg * 0.70710678118654752440f));
                d_act[(size_t)r*Hh + jc] = uu * gel * mb[e*Hh + jc];
            }
        }
    }
}

// =====================  GEMM2: act @ w2 -> expert_out ======================
__global__ void gemm2_kernel(const float* __restrict__ w2,
                             const float* __restrict__ b2) {
    __shared__ float As[16][65];
    __shared__ float Bs[16][64];
    int g = blockIdx.z, e = g & 7;
    int rowbase = g*CAP + blockIdx.y*64;
    int j0 = blockIdx.x*64;
    int tid = threadIdx.x;
    int tx = tid & 15, ty = tid >> 4;
    float acc[4][4] = {};
    const float* w2e = w2 + (size_t)e * Hh * Dd;

    for (int k0 = 0; k0 < Hh; k0 += 16) {
        {   // A tile (scalar, ld=1365 odd)
            int m = tid >> 2, kq = (tid & 3)*4;
#pragma unroll
            for (int q = 0; q < 4; q++) {
                int kk = k0 + kq + q;
                As[kq+q][m] = (kk < Hh)
                    ? d_act[(size_t)(rowbase + m)*Hh + kk] : 0.f;
            }
        }
        {   // B tile (float4, ld=512)
            int kb = tid >> 4, jj = (tid & 15)*4;
            int kk = k0 + kb;
            float4 bv = make_float4(0.f, 0.f, 0.f, 0.f);
            if (kk < Hh)
                bv = *reinterpret_cast<const float4*>(w2e + (size_t)kk*Dd + j0 + jj);
            Bs[kb][jj+0] = bv.x; Bs[kb][jj+1] = bv.y;
            Bs[kb][jj+2] = bv.z; Bs[kb][jj+3] = bv.w;
        }
        __syncthreads();
#pragma unroll
        for (int k = 0; k < 16; k++) {
            float a[4], bb[4];
#pragma unroll
            for (int i = 0; i < 4; i++) a[i] = As[k][ty*4 + i];
#pragma unroll
            for (int j = 0; j < 4; j++) bb[j] = Bs[k][tx*4 + j];
#pragma unroll
            for (int i = 0; i < 4; i++)
#pragma unroll
                for (int j = 0; j < 4; j++) acc[i][j] += a[i]*bb[j];
        }
        __syncthreads();
    }
#pragma unroll
    for (int i = 0; i < 4; i++)
#pragma unroll
        for (int j = 0; j < 4; j++) {
            int r = rowbase + ty*4 + i;
            int jc = j0 + tx*4 + j;
            d_eo[(size_t)r*Dd + jc] = acc[i][j] + b2[e*Dd + jc];
        }
}

// =====================  combine + residual + LayerNorm ======================
__global__ void final_kernel(const float* __restrict__ x,
                             const float* __restrict__ lng,
                             const float* __restrict__ lnb,
                             float* __restrict__ out) {
    int t = blockIdx.x;
    int tid = threadIdx.x;        // 128 threads
    int s0 = d_s0[t], s1 = d_s1[t];
    float g0 = d_g0[t], g1 = d_g1[t];
    float y[4];
#pragma unroll
    for (int i = 0; i < 4; i++) {
        int d = tid + i*128;
        float acc = x[(size_t)t*Dd + d];
        if (s0 >= 0) acc += g0 * d_eo[(size_t)s0*Dd + d];
        if (s1 >= 0) acc += g1 * d_eo[(size_t)s1*Dd + d];
        y[i] = acc;
    }
    __shared__ float s_red[128];
    float s = y[0] + y[1] + y[2] + y[3];
    s_red[tid] = s;
    __syncthreads();
    for (int st = 64; st > 0; st >>= 1) {
        if (tid < st) s_red[tid] += s_red[tid + st];
        __syncthreads();
    }
    float mu = s_red[0] / (float)Dd;
    __syncthreads();
    float sv = 0.f;
#pragma unroll
    for (int i = 0; i < 4; i++) { float dvv = y[i] - mu; sv += dvv * dvv; }
    s_red[tid] = sv;
    __syncthreads();
    for (int st = 64; st > 0; st >>= 1) {
        if (tid < st) s_red[tid] += s_red[tid + st];
        __syncthreads();
    }
    float var = s_red[0] / (float)Dd;
    float rstd = rsqrtf(var + 1e-5f);
#pragma unroll
    for (int i = 0; i < 4; i++) {
        int d = tid + i*128;
        out[(size_t)t*Dd + d] = (y[i] - mu) * rstd * lng[d] + lnb[d];
    }
}

// =====================  aux-loss scalar ======================
__global__ void aux_kernel(float* __restrict__ out, int out_size) {
    int tid = threadIdx.x;   // 32
    float v = (d_gsum[tid] / (float)Nn) * ((float)d_c0cnt[tid] / (float)Nn);
#pragma unroll
    for (int o = 16; o > 0; o >>= 1) v += __shfl_down_sync(0xffffffffu, v, o);
    if (tid == 0) {
        float bal = (v / (float)(Bb*Ee)) * (float)(Ee*Ee);
        float rz = d_zsum / (float)NTOK;
        float aux = 0.01f * bal + 0.001f * rz;
        for (int i = BND; i < out_size; i++) out[i] = aux;
    }
}

// =====================  launch ======================
extern "C" void kernel_launch(void* const* d_in, const int* in_sizes, int n_in,
                              void* d_out, int out_size) {
    const float* x   = (const float*)d_in[0];
    const float* gw  = (const float*)d_in[1];
    const float* pg  = (const float*)d_in[2];
    const float* w1  = (const float*)d_in[3];
    const float* b1  = (const float*)d_in[4];
    const float* mb  = (const float*)d_in[5];
    const float* w2  = (const float*)d_in[6];
    const float* b2  = (const float*)d_in[7];
    const float* lng = (const float*)d_in[8];
    const float* lnb = (const float*)d_in[9];
    float* out = (float*)d_out;

    init_kernel<<<(NSLOT + 255)/256, 256>>>();
    token_kernel<<<NTOK, 128>>>(x, gw, pg);
    scan_kernel<<<Bb, 32>>>();
    gather_kernel<<<NSLOT, 128>>>();
    gemm1_kernel<<<dim3((Hh + 63)/64, CAP/64, Bb*Ee), 256>>>(w1, b1, mb);
    gemm2_kernel<<<dim3(Dd/64, CAP/64, Bb*Ee), 256>>>(w2, b2);
    final_kernel<<<NTOK, 128>>>(x, lng, lnb, out);
    aux_kernel<<<1, 32>>>(out, out_size);
}

// round 5
// speedup vs baseline: 3.4903x; 3.4903x over previous
#include <cuda_runtime.h>
#include <cuda_bf16.h>
#include <math.h>
#include <stdint.h>

// ---- problem constants ----
#define Bb   4
#define Nn   2048
#define Dd   512
#define Ee   8
#define Hh   1365
#define H2   2730
#define CAP  320
#define RPG  384                 // padded rows per (b,e) group (320 -> 3*128)
#define NGRP (Bb*Ee)             // 32
#define ROWS (NGRP*RPG)          // 12288
#define NTOK (Bb*Nn)             // 8192
#define BND  (Bb*Nn*Dd)          // 4194304
#define NP1  2816                // padded interleaved N for gemm1 (22*128)
#define KP2  1408                // padded K for gemm2 (44*32)

// ---- scratch ----
__device__ __align__(16) float         d_xg[BND];
__device__ __align__(16) __nv_bfloat16 d_einbf[ROWS*Dd];
__device__ __align__(16) __nv_bfloat16 d_actbf[(size_t)ROWS*KP2];
__device__ __align__(16) float         d_eo[(size_t)ROWS*Dd];
__device__ __align__(16) __nv_bfloat16 d_w1bf[(size_t)Ee*NP1*Dd];
__device__ __align__(16) __nv_bfloat16 d_w2bf[(size_t)Ee*Dd*KP2];
__device__ int   d_e0[NTOK], d_e1[NTOK], d_r1[NTOK];
__device__ float d_g0[NTOK], d_g1[NTOK];
__device__ int   d_s0[NTOK], d_s1[NTOK];
__device__ int   d_slot_tok[ROWS];
__device__ float d_gsum[Bb*Ee];
__device__ int   d_c0cnt[Bb*Ee];
__device__ float d_zsum;

// =====================  PTX helpers (baseline ISA only)  ======================
__device__ __forceinline__ uint32_t smem_u32(const void* p) {
    uint32_t a;
    asm("{ .reg .u64 t; cvta.to.shared.u64 t, %1; cvt.u32.u64 %0, t; }"
        : "=r"(a) : "l"(p));
    return a;
}
__device__ __forceinline__ void cpasync16(uint32_t dst, const void* src) {
    asm volatile("cp.async.cg.shared.global [%0], [%1], 16;"
                 :: "r"(dst), "l"(src) : "memory");
}
#define CP_COMMIT() asm volatile("cp.async.commit_group;" ::: "memory")
#define CP_WAIT2()  asm volatile("cp.async.wait_group 2;" ::: "memory")

__device__ __forceinline__ void ldsm4(uint32_t* r, uint32_t addr) {
    asm volatile("ldmatrix.sync.aligned.m8n8.x4.shared.b16 {%0,%1,%2,%3}, [%4];"
                 : "=r"(r[0]), "=r"(r[1]), "=r"(r[2]), "=r"(r[3]) : "r"(addr));
}
__device__ __forceinline__ void mma16816(float* c, const uint32_t* a,
                                         uint32_t b0, uint32_t b1) {
    asm volatile(
        "mma.sync.aligned.m16n8k16.row.col.f32.bf16.bf16.f32 "
        "{%0,%1,%2,%3}, {%4,%5,%6,%7}, {%8,%9}, {%0,%1,%2,%3};"
        : "+f"(c[0]), "+f"(c[1]), "+f"(c[2]), "+f"(c[3])
        : "r"(a[0]), "r"(a[1]), "r"(a[2]), "r"(a[3]), "r"(b0), "r"(b1));
}

// swizzled smem offset for a [128 rows][32 cols bf16] tile (64B/row, 8KB total)
// rows paired into 128B super-rows; 16B chunk index XORed with super-row.
__device__ __forceinline__ uint32_t swz(int r, int c) {
    int ra = r >> 1, rb = r & 1;
    return (uint32_t)((ra << 7) + ((((rb << 2) | c) ^ (ra & 7)) << 4));
}

// =====================  JAX threefry (partitionable)  ======================
__device__ __forceinline__ unsigned rotl32(unsigned x, int d) {
    return (x << d) | (x >> (32 - d));
}
__device__ float jax_uniform_idx(unsigned idx) {
    const unsigned k0 = 0u, k1 = 42u;
    const unsigned k2 = k0 ^ k1 ^ 0x1BD11BDAu;
    unsigned x0 = 0u + k0;
    unsigned x1 = idx + k1;
#define TF_RND(r) { x0 += x1; x1 = rotl32(x1, r); x1 ^= x0; }
    TF_RND(13) TF_RND(15) TF_RND(26) TF_RND(6)   x0 += k1; x1 += k2 + 1u;
    TF_RND(17) TF_RND(29) TF_RND(16) TF_RND(24)  x0 += k2; x1 += k0 + 2u;
    TF_RND(13) TF_RND(15) TF_RND(26) TF_RND(6)   x0 += k0; x1 += k1 + 3u;
    TF_RND(17) TF_RND(29) TF_RND(16) TF_RND(24)  x0 += k1; x1 += k2 + 4u;
    TF_RND(13) TF_RND(15) TF_RND(26) TF_RND(6)   x0 += k2; x1 += k0 + 5u;
#undef TF_RND
    unsigned bits = x0 ^ x1;
    return __uint_as_float((bits >> 9) | 0x3f800000u) - 1.0f;
}

// =====================  init  ======================
__global__ void init_kernel() {
    int i = blockIdx.x * blockDim.x + threadIdx.x;
    if (i < ROWS)  d_slot_tok[i] = -1;
    if (i < Bb*Ee) d_gsum[i] = 0.f;
    if (i == 0)    d_zsum = 0.f;
}

// =====================  per-token: rmsnorm + router  ======================
__global__ void token_kernel(const float* __restrict__ x,
                             const float* __restrict__ gw,
                             const float* __restrict__ pg) {
    int t = blockIdx.x;
    int tid = threadIdx.x;          // 128
    int b = t / Nn;
    const float* xr = x + (size_t)t * Dd;

    float xv[4];
    float ss = 0.f;
#pragma unroll
    for (int i = 0; i < 4; i++) {
        float v = xr[tid + i*128];
        xv[i] = v;
        ss += v * v;
    }
    __shared__ float s_red[128];
    s_red[tid] = ss;
    __syncthreads();
    for (int s = 64; s > 0; s >>= 1) {
        if (tid < s) s_red[tid] += s_red[tid + s];
        __syncthreads();
    }
    float nrm = fmaxf(sqrtf(s_red[0]), 1e-12f);
    float scale = 22.627416997969520780827019587355f / nrm;

    float p[Ee];
#pragma unroll
    for (int e = 0; e < Ee; e++) p[e] = 0.f;
#pragma unroll
    for (int i = 0; i < 4; i++) {
        int d = tid + i*128;
        float v = xv[i] * scale * pg[d];
        d_xg[(size_t)t * Dd + d] = v;
#pragma unroll
        for (int e = 0; e < Ee; e++) p[e] += v * gw[d*Ee + e];
    }
    __shared__ float s_l[Ee][128];
#pragma unroll
    for (int e = 0; e < Ee; e++) s_l[e][tid] = p[e];
    __syncthreads();
    for (int s = 64; s > 0; s >>= 1) {
        if (tid < s)
#pragma unroll
            for (int e = 0; e < Ee; e++) s_l[e][tid] += s_l[e][tid + s];
        __syncthreads();
    }
    if (tid == 0) {
        float lg[Ee], mx = -1e30f;
#pragma unroll
        for (int e = 0; e < Ee; e++) { lg[e] = s_l[e][0]; mx = fmaxf(mx, lg[e]); }
        float se = 0.f, ge[Ee];
#pragma unroll
        for (int e = 0; e < Ee; e++) { ge[e] = expf(lg[e] - mx); se += ge[e]; }
#pragma unroll
        for (int e = 0; e < Ee; e++) ge[e] = ge[e] / se;
        float z = mx + logf(se);
        atomicAdd(&d_zsum, z * z);
#pragma unroll
        for (int e = 0; e < Ee; e++) atomicAdd(&d_gsum[b*Ee + e], ge[e]);
        float m1 = -1e30f, m2 = -1e30f; int i1 = 0, i2 = 0;
#pragma unroll
        for (int e = 0; e < Ee; e++) {
            float v = ge[e];
            if (v > m1)      { m2 = m1; i2 = i1; m1 = v; i1 = e; }
            else if (v > m2) { m2 = v;  i2 = e; }
        }
        float denom = fmaxf(m1 + m2, 1e-9f);
        float g0 = m1 / denom, g1 = m2 / denom;
        float prob = jax_uniform_idx(8192u + (unsigned)t);
        int r1 = prob < (g1 / 0.2f);
        d_e0[t] = i1; d_e1[t] = i2;
        d_g0[t] = g0; d_g1[t] = g1;
        d_r1[t] = r1;
    }
}

// =====================  capacity scan  ======================
__global__ void scan_kernel() {
    int b = blockIdx.x;
    int lane = threadIdx.x;
    unsigned ltmask = (1u << lane) - 1u;

    int cnt[Ee];
#pragma unroll
    for (int e = 0; e < Ee; e++) cnt[e] = 0;

    for (int c = 0; c < Nn/32; c++) {
        int n = c*32 + lane;
        int t = b*Nn + n;
        int e = d_e0[t];
        int pos = 0;
#pragma unroll
        for (int ei = 0; ei < Ee; ei++) {
            unsigned bal = __ballot_sync(0xffffffffu, e == ei);
            if (e == ei) pos = cnt[ei] + __popc(bal & ltmask);
            cnt[ei] += __popc(bal);
        }
        if (pos < CAP) {
            int slot = (b*Ee + e)*RPG + pos;
            d_slot_tok[slot] = n;
            d_s0[t] = slot;
        } else {
            d_s0[t] = -1;
        }
    }
    int c0[Ee];
#pragma unroll
    for (int e = 0; e < Ee; e++) c0[e] = min(cnt[e], CAP);
    if (lane < Ee) d_c0cnt[b*Ee + lane] = c0[lane];

    int cnt1[Ee];
#pragma unroll
    for (int e = 0; e < Ee; e++) cnt1[e] = 0;
    for (int c = 0; c < Nn/32; c++) {
        int n = c*32 + lane;
        int t = b*Nn + n;
        int e = d_r1[t] ? d_e1[t] : -1;
        int posl = 0;
#pragma unroll
        for (int ei = 0; ei < Ee; ei++) {
            unsigned bal = __ballot_sync(0xffffffffu, e == ei);
            if (e == ei) posl = cnt1[ei] + __popc(bal & ltmask);
            cnt1[ei] += __popc(bal);
        }
        if (e >= 0) {
            int pos = c0[e] + posl;
            if (pos < CAP) {
                int slot = (b*Ee + e)*RPG + pos;
                d_slot_tok[slot] = n;
                d_s1[t] = slot;
            } else {
                d_s1[t] = -1;
            }
        } else {
            d_s1[t] = -1;
        }
    }
}

// =====================  weight conversion  ======================
// w1: [e][k=512][2730] fp32 -> d_w1bf [e][c=2816][k=512] bf16,
// col c<2730 maps to src col (c&1)*1365 + (c>>1)  (u/g interleave)
__global__ void convw1_kernel(const float* __restrict__ w1) {
    __shared__ float t[32][33];
    int e = blockIdx.z, k0 = blockIdx.y*32, c0 = blockIdx.x*32;
    int tx = threadIdx.x & 31, ty = threadIdx.x >> 5;   // 256 thr = 32x8
#pragma unroll
    for (int i = 0; i < 4; i++) {
        int k = k0 + ty + i*8, c = c0 + tx;
        float v = 0.f;
        if (c < H2) {
            int m = (c & 1)*Hh + (c >> 1);
            v = w1[((size_t)e*Dd + k)*H2 + m];
        }
        t[ty + i*8][tx] = v;
    }
    __syncthreads();
#pragma unroll
    for (int i = 0; i < 4; i++) {
        int c = c0 + ty + i*8, k = k0 + tx;
        d_w1bf[((size_t)e*NP1 + c)*Dd + k] = __float2bfloat16(t[tx][ty + i*8]);
    }
}
// w2: [e][k=1365][512] fp32 -> d_w2bf [e][n=512][k=1408] bf16 (k pad zero)
__global__ void convw2_kernel(const float* __restrict__ w2) {
    __shared__ float t[32][33];
    int e = blockIdx.z, k0 = blockIdx.y*32, n0 = blockIdx.x*32;
    int tx = threadIdx.x & 31, ty = threadIdx.x >> 5;
#pragma unroll
    for (int i = 0; i < 4; i++) {
        int k = k0 + ty + i*8, n = n0 + tx;
        float v = 0.f;
        if (k < Hh) v = w2[((size_t)e*Hh + k)*Dd + n];
        t[ty + i*8][tx] = v;
    }
    __syncthreads();
#pragma unroll
    for (int i = 0; i < 4; i++) {
        int n = n0 + ty + i*8, k = k0 + tx;
        d_w2bf[((size_t)e*Dd + n)*KP2 + k] = __float2bfloat16(t[tx][ty + i*8]);
    }
}

// =====================  gather xg rows into padded slot layout (bf16) =========
__global__ void gather_kernel() {
    int r = blockIdx.x;
    int tid = threadIdx.x;   // 128
    int tok = d_slot_tok[r];
    int b = r / (Ee*RPG);
    int d0 = tid * 4;
    float4 v = make_float4(0.f, 0.f, 0.f, 0.f);
    if (tok >= 0)
        v = *(const float4*)(d_xg + ((size_t)(b*Nn + tok))*Dd + d0);
    __nv_bfloat162 lo = __floats2bfloat162_rn(v.x, v.y);
    __nv_bfloat162 hi = __floats2bfloat162_rn(v.z, v.w);
    *(__nv_bfloat162*)(d_einbf + (size_t)r*Dd + d0)     = lo;
    *(__nv_bfloat162*)(d_einbf + (size_t)r*Dd + d0 + 2) = hi;
}

// =====================  HMMA mainloop (128x128x32 tile, 3-stage cp.async) ====
// warp grid 2(M) x 4(N); per-warp 64x32; accum acc[4 m16][4 n8][4]
template<int KT>
__device__ __forceinline__ void run_gemm(
        const __nv_bfloat16* __restrict__ Ag, int ldA,
        const __nv_bfloat16* __restrict__ Bg, int ldB,
        uint32_t sA, uint32_t sB, float acc[4][4][4], int tid)
{
    int lane = tid & 31, w = tid >> 5;
    int wm = w & 1, wn = w >> 1;
    int rA = wm*64 + (lane & 15);
    int cA = lane >> 4;
    int rB = wn*32 + (lane & 7) + ((lane >> 4) << 3);
    int cB = (lane >> 3) & 1;

    // preload stages 0,1
#pragma unroll
    for (int p = 0; p < 2; p++) {
        uint32_t dA = sA + p*8192, dB = sB + p*8192;
        const __nv_bfloat16* Akt = Ag + p*32;
        const __nv_bfloat16* Bkt = Bg + p*32;
#pragma unroll
        for (int i = 0; i < 2; i++) {
            int idx = i*256 + tid;
            int r = idx >> 2, c = idx & 3;
            cpasync16(dA + swz(r, c), Akt + (size_t)r*ldA + c*8);
            cpasync16(dB + swz(r, c), Bkt + (size_t)r*ldB + c*8);
        }
        CP_COMMIT();
    }

#pragma unroll 1
    for (int kt = 0; kt < KT; kt++) {
        if (kt + 2 < KT) {
            int st2 = (kt + 2) % 3;
            uint32_t dA = sA + st2*8192, dB = sB + st2*8192;
            const __nv_bfloat16* Akt = Ag + (kt + 2)*32;
            const __nv_bfloat16* Bkt = Bg + (kt + 2)*32;
#pragma unroll
            for (int i = 0; i < 2; i++) {
                int idx = i*256 + tid;
                int r = idx >> 2, c = idx & 3;
                cpasync16(dA + swz(r, c), Akt + (size_t)r*ldA + c*8);
                cpasync16(dB + swz(r, c), Bkt + (size_t)r*ldB + c*8);
            }
        }
        CP_COMMIT();       // empty groups at tail keep wait-count semantics
        CP_WAIT2();
        __syncthreads();

        int st = kt % 3;
        uint32_t aA = sA + st*8192, aB = sB + st*8192;
#pragma unroll
        for (int ks = 0; ks < 2; ks++) {
            uint32_t a[4][4], b[2][4];
#pragma unroll
            for (int mi = 0; mi < 4; mi++)
                ldsm4(a[mi], aA + swz(rA + mi*16, ks*2 + cA));
#pragma unroll
            for (int nj = 0; nj < 2; nj++)
                ldsm4(b[nj], aB + swz(rB + nj*16, ks*2 + cB));
#pragma unroll
            for (int mi = 0; mi < 4; mi++)
#pragma unroll
                for (int n8 = 0; n8 < 4; n8++)
                    mma16816(acc[mi][n8], a[mi],
                             b[n8 >> 1][(n8 & 1)*2], b[n8 >> 1][(n8 & 1)*2 + 1]);
        }
        __syncthreads();
    }
}

// =====================  GEMM1 (HMMA) + GEGLU epilogue ======================
__global__ void __launch_bounds__(256, 2) gemm1_mma(const float* __restrict__ b1,
                                                    const float* __restrict__ mb) {
    __shared__ __align__(1024) char sAbuf[3][8192];
    __shared__ __align__(1024) char sBbuf[3][8192];
    int tid = threadIdx.x;
    int grp = blockIdx.z, e = grp & 7, mt = blockIdx.y, nt = blockIdx.x;
    const __nv_bfloat16* Ag = d_einbf + (size_t)(grp*RPG + mt*128)*Dd;
    const __nv_bfloat16* Bg = d_w1bf + ((size_t)e*NP1 + nt*128)*Dd;

    float acc[4][4][4] = {};
    run_gemm<16>(Ag, Dd, Bg, Dd, smem_u32(sAbuf), smem_u32(sBbuf), acc, tid);

    int lane = tid & 31, w = tid >> 5;
    int wm = w & 1, wn = w >> 1;
    int g = lane >> 2, tc = lane & 3;
    int rowbase = grp*RPG + mt*128 + wm*64;
    int ncolbase = nt*128 + wn*32;
#pragma unroll
    for (int n8 = 0; n8 < 4; n8++) {
        int j = (ncolbase + n8*8 + tc*2) >> 1;
        float b1u = 0.f, b1g = 0.f, mbv = 0.f;
        if (j < Hh) {
            b1u = b1[e*H2 + j];
            b1g = b1[e*H2 + Hh + j];
            mbv = mb[e*Hh + j];
        }
#pragma unroll
        for (int mi = 0; mi < 4; mi++)
#pragma unroll
            for (int half = 0; half < 2; half++) {
                int row = rowbase + mi*16 + g + half*8;
                float av = 0.f;
                if (j < Hh) {
                    float u  = acc[mi][n8][half*2 + 0] + b1u;
                    float gg = acc[mi][n8][half*2 + 1] + b1g;
                    float gel = 0.5f * gg * (1.f + erff(gg * 0.70710678118654752440f));
                    av = u * gel * mbv;
                }
                d_actbf[(size_t)row*KP2 + j] = __float2bfloat16(av);
            }
    }
}

// =====================  GEMM2 (HMMA) + bias epilogue ======================
__global__ void __launch_bounds__(256, 2) gemm2_mma(const float* __restrict__ b2) {
    __shared__ __align__(1024) char sAbuf[3][8192];
    __shared__ __align__(1024) char sBbuf[3][8192];
    int tid = threadIdx.x;
    int grp = blockIdx.z, e = grp & 7, mt = blockIdx.y, nt = blockIdx.x;
    const __nv_bfloat16* Ag = d_actbf + (size_t)(grp*RPG + mt*128)*KP2;
    const __nv_bfloat16* Bg = d_w2bf + ((size_t)e*Dd + nt*128)*KP2;

    float acc[4][4][4] = {};
    run_gemm<44>(Ag, KP2, Bg, KP2, smem_u32(sAbuf), smem_u32(sBbuf), acc, tid);

    int lane = tid & 31, w = tid >> 5;
    int wm = w & 1, wn = w >> 1;
    int g = lane >> 2, tc = lane & 3;
    int rowbase = grp*RPG + mt*128 + wm*64;
    int ncolbase = nt*128 + wn*32;
#pragma unroll
    for (int n8 = 0; n8 < 4; n8++) {
        int ncol = ncolbase + n8*8 + tc*2;
        float bz0 = b2[e*Dd + ncol];
        float bz1 = b2[e*Dd + ncol + 1];
#pragma unroll
        for (int mi = 0; mi < 4; mi++)
#pragma unroll
            for (int half = 0; half < 2; half++) {
                int row = rowbase + mi*16 + g + half*8;
                float2 v;
                v.x = acc[mi][n8][half*2 + 0] + bz0;
                v.y = acc[mi][n8][half*2 + 1] + bz1;
                *(float2*)(d_eo + (size_t)row*Dd + ncol) = v;
            }
    }
}

// =====================  combine + residual + LayerNorm ======================
__global__ void final_kernel(const float* __restrict__ x,
                             const float* __restrict__ lng,
                             const float* __restrict__ lnb,
                             float* __restrict__ out) {
    int t = blockIdx.x;
    int tid = threadIdx.x;   // 128
    int s0 = d_s0[t], s1 = d_s1[t];
    float g0 = d_g0[t], g1 = d_g1[t];
    float y[4];
#pragma unroll
    for (int i = 0; i < 4; i++) {
        int d = tid + i*128;
        float acc = x[(size_t)t*Dd + d];
        if (s0 >= 0) acc += g0 * d_eo[(size_t)s0*Dd + d];
        if (s1 >= 0) acc += g1 * d_eo[(size_t)s1*Dd + d];
        y[i] = acc;
    }
    __shared__ float s_red[128];
    float s = y[0] + y[1] + y[2] + y[3];
    s_red[tid] = s;
    __syncthreads();
    for (int st = 64; st > 0; st >>= 1) {
        if (tid < st) s_red[tid] += s_red[tid + st];
        __syncthreads();
    }
    float mu = s_red[0] / (float)Dd;
    __syncthreads();
    float sv = 0.f;
#pragma unroll
    for (int i = 0; i < 4; i++) { float dv = y[i] - mu; sv += dv * dv; }
    s_red[tid] = sv;
    __syncthreads();
    for (int st = 64; st > 0; st >>= 1) {
        if (tid < st) s_red[tid] += s_red[tid + st];
        __syncthreads();
    }
    float var = s_red[0] / (float)Dd;
    float rstd = rsqrtf(var + 1e-5f);
#pragma unroll
    for (int i = 0; i < 4; i++) {
        int d = tid + i*128;
        out[(size_t)t*Dd + d] = (y[i] - mu) * rstd * lng[d] + lnb[d];
    }
}

// =====================  aux-loss scalar ======================
__global__ void aux_kernel(float* __restrict__ out, int out_size) {
    int tid = threadIdx.x;   // 32
    float v = (d_gsum[tid] / (float)Nn) * ((float)d_c0cnt[tid] / (float)Nn);
#pragma unroll
    for (int o = 16; o > 0; o >>= 1) v += __shfl_down_sync(0xffffffffu, v, o);
    if (tid == 0) {
        float bal = (v / (float)(Bb*Ee)) * (float)(Ee*Ee);
        float rz = d_zsum / (float)NTOK;
        float aux = 0.01f * bal + 0.001f * rz;
        for (int i = BND; i < out_size; i++) out[i] = aux;
    }
}

// =====================  launch ======================
extern "C" void kernel_launch(void* const* d_in, const int* in_sizes, int n_in,
                              void* d_out, int out_size) {
    const float* x   = (const float*)d_in[0];
    const float* gw  = (const float*)d_in[1];
    const float* pg  = (const float*)d_in[2];
    const float* w1  = (const float*)d_in[3];
    const float* b1  = (const float*)d_in[4];
    const float* mb  = (const float*)d_in[5];
    const float* w2  = (const float*)d_in[6];
    const float* b2  = (const float*)d_in[7];
    const float* lng = (const float*)d_in[8];
    const float* lnb = (const float*)d_in[9];
    float* out = (float*)d_out;

    init_kernel<<<(ROWS + 255)/256, 256>>>();
    token_kernel<<<NTOK, 128>>>(x, gw, pg);
    scan_kernel<<<Bb, 32>>>();
    convw1_kernel<<<dim3(NP1/32, Dd/32, Ee), 256>>>(w1);
    convw2_kernel<<<dim3(Dd/32, KP2/32, Ee), 256>>>(w2);
    gather_kernel<<<ROWS, 128>>>();
    gemm1_mma<<<dim3(NP1/128, RPG/128, NGRP), 256>>>(b1, mb);
    gemm2_mma<<<dim3(Dd/128, RPG/128, NGRP), 256>>>(b2);
    final_kernel<<<NTOK, 128>>>(x, lng, lnb, out);
    aux_kernel<<<1, 32>>>(out, out_size);
}

// round 6
// speedup vs baseline: 4.9208x; 1.4098x over previous
#include <cuda_runtime.h>
#include <cuda_bf16.h>
#include <math.h>
#include <stdint.h>

// ---- problem constants ----
#define Bb   4
#define Nn   2048
#define Dd   512
#define Ee   8
#define Hh   1365
#define H2   2730
#define CAP  320
#define RPG  320                 // rows per (b,e) group (exact, 2*128 + 64)
#define NGRP (Bb*Ee)             // 32
#define ROWS (NGRP*RPG)          // 10240
#define NTOK (Bb*Nn)             // 8192
#define BND  (Bb*Nn*Dd)          // 4194304
#define NP1  2816                // padded interleaved N for gemm1 (22*128)
#define KP2  1408                // padded K for gemm2 (44*32)

// ---- scratch ----
__device__ __align__(16) float         d_xg[BND];
__device__ __align__(16) __nv_bfloat16 d_einbf[ROWS*Dd];
__device__ __align__(16) __nv_bfloat16 d_actbf[(size_t)ROWS*KP2];
__device__ __align__(16) float         d_eo[(size_t)ROWS*Dd];
__device__ __align__(16) __nv_bfloat16 d_w1bf[(size_t)Ee*NP1*Dd];
__device__ __align__(16) __nv_bfloat16 d_w2bf[(size_t)Ee*Dd*KP2];
__device__ int   d_e0[NTOK], d_e1[NTOK], d_r1[NTOK];
__device__ float d_g0[NTOK], d_g1[NTOK];
__device__ int   d_s0[NTOK], d_s1[NTOK];
__device__ int   d_slot_tok[ROWS];
__device__ float d_gsum[Bb*Ee];
__device__ int   d_c0cnt[Bb*Ee];
__device__ float d_zsum;

// =====================  PTX helpers (baseline ISA only)  ======================
__device__ __forceinline__ uint32_t smem_u32(const void* p) {
    uint32_t a;
    asm("{ .reg .u64 t; cvta.to.shared.u64 t, %1; cvt.u32.u64 %0, t; }"
        : "=r"(a) : "l"(p));
    return a;
}
__device__ __forceinline__ void cpasync16(uint32_t dst, const void* src) {
    asm volatile("cp.async.cg.shared.global [%0], [%1], 16;"
                 :: "r"(dst), "l"(src) : "memory");
}
#define CP_COMMIT() asm volatile("cp.async.commit_group;" ::: "memory")
#define CP_WAIT1()  asm volatile("cp.async.wait_group 1;" ::: "memory")

__device__ __forceinline__ void ldsm4(uint32_t* r, uint32_t addr) {
    asm volatile("ldmatrix.sync.aligned.m8n8.x4.shared.b16 {%0,%1,%2,%3}, [%4];"
                 : "=r"(r[0]), "=r"(r[1]), "=r"(r[2]), "=r"(r[3]) : "r"(addr));
}
__device__ __forceinline__ void mma16816(float* c, const uint32_t* a,
                                         uint32_t b0, uint32_t b1) {
    asm volatile(
        "mma.sync.aligned.m16n8k16.row.col.f32.bf16.bf16.f32 "
        "{%0,%1,%2,%3}, {%4,%5,%6,%7}, {%8,%9}, {%0,%1,%2,%3};"
        : "+f"(c[0]), "+f"(c[1]), "+f"(c[2]), "+f"(c[3])
        : "r"(a[0]), "r"(a[1]), "r"(a[2]), "r"(a[3]), "r"(b0), "r"(b1));
}

// swizzled smem offset for a [rows][32 cols bf16] tile (64B/row)
__device__ __forceinline__ uint32_t swz(int r, int c) {
    int ra = r >> 1, rb = r & 1;
    return (uint32_t)((ra << 7) + ((((rb << 2) | c) ^ (ra & 7)) << 4));
}

// =====================  JAX threefry (partitionable)  ======================
__device__ __forceinline__ unsigned rotl32(unsigned x, int d) {
    return (x << d) | (x >> (32 - d));
}
__device__ float jax_uniform_idx(unsigned idx) {
    const unsigned k0 = 0u, k1 = 42u;
    const unsigned k2 = k0 ^ k1 ^ 0x1BD11BDAu;
    unsigned x0 = 0u + k0;
    unsigned x1 = idx + k1;
#define TF_RND(r) { x0 += x1; x1 = rotl32(x1, r); x1 ^= x0; }
    TF_RND(13) TF_RND(15) TF_RND(26) TF_RND(6)   x0 += k1; x1 += k2 + 1u;
    TF_RND(17) TF_RND(29) TF_RND(16) TF_RND(24)  x0 += k2; x1 += k0 + 2u;
    TF_RND(13) TF_RND(15) TF_RND(26) TF_RND(6)   x0 += k0; x1 += k1 + 3u;
    TF_RND(17) TF_RND(29) TF_RND(16) TF_RND(24)  x0 += k1; x1 += k2 + 4u;
    TF_RND(13) TF_RND(15) TF_RND(26) TF_RND(6)   x0 += k2; x1 += k0 + 5u;
#undef TF_RND
    unsigned bits = x0 ^ x1;
    return __uint_as_float((bits >> 9) | 0x3f800000u) - 1.0f;
}

// =====================  init  ======================
__global__ void init_kernel() {
    int i = blockIdx.x * blockDim.x + threadIdx.x;
    if (i < ROWS)  d_slot_tok[i] = -1;
    if (i < Bb*Ee) d_gsum[i] = 0.f;
    if (i == 0)    d_zsum = 0.f;
}

// =====================  per-token: rmsnorm + router (warp per token) =========
__global__ void __launch_bounds__(256) token_kernel(
        const float* __restrict__ x,
        const float* __restrict__ gw,
        const float* __restrict__ pg) {
    int warp = threadIdx.x >> 5;
    int lane = threadIdx.x & 31;
    int t = blockIdx.x*8 + warp;
    int b = t >> 11;                 // t / 2048
    const float* xr = x + (size_t)t * Dd;

    float xv[16];
    float ss = 0.f;
#pragma unroll
    for (int j = 0; j < 16; j++) {
        float v = xr[lane + j*32];
        xv[j] = v;
        ss += v * v;
    }
#pragma unroll
    for (int o = 16; o > 0; o >>= 1) ss += __shfl_xor_sync(0xffffffffu, ss, o);
    float scale = 22.627416997969520780827019587355f / fmaxf(sqrtf(ss), 1e-12f);

    float p[Ee];
#pragma unroll
    for (int e = 0; e < Ee; e++) p[e] = 0.f;
#pragma unroll
    for (int j = 0; j < 16; j++) {
        int d = lane + j*32;
        float v = xv[j] * scale * pg[d];
        d_xg[(size_t)t*Dd + d] = v;
#pragma unroll
        for (int e = 0; e < Ee; e++) p[e] += v * gw[d*Ee + e];
    }
#pragma unroll
    for (int o = 16; o > 0; o >>= 1)
#pragma unroll
        for (int e = 0; e < Ee; e++) p[e] += __shfl_xor_sync(0xffffffffu, p[e], o);

    __shared__ float s_g[Ee];
    __shared__ float s_z;
    if (threadIdx.x < Ee) s_g[threadIdx.x] = 0.f;
    if (threadIdx.x == 0) s_z = 0.f;
    __syncthreads();

    if (lane == 0) {
        float mx = -1e30f;
#pragma unroll
        for (int e = 0; e < Ee; e++) mx = fmaxf(mx, p[e]);
        float se = 0.f, ge[Ee];
#pragma unroll
        for (int e = 0; e < Ee; e++) { ge[e] = expf(p[e] - mx); se += ge[e]; }
        float inv = 1.f / se;
#pragma unroll
        for (int e = 0; e < Ee; e++) ge[e] *= inv;
        float z = mx + logf(se);
        atomicAdd(&s_z, z * z);
#pragma unroll
        for (int e = 0; e < Ee; e++) atomicAdd(&s_g[e], ge[e]);
        float m1 = -1e30f, m2 = -1e30f; int i1 = 0, i2 = 0;
#pragma unroll
        for (int e = 0; e < Ee; e++) {
            float v = ge[e];
            if (v > m1)      { m2 = m1; i2 = i1; m1 = v; i1 = e; }
            else if (v > m2) { m2 = v;  i2 = e; }
        }
        float denom = fmaxf(m1 + m2, 1e-9f);
        float g0 = m1 / denom, g1 = m2 / denom;
        float prob = jax_uniform_idx(8192u + (unsigned)t);
        d_e0[t] = i1; d_e1[t] = i2;
        d_g0[t] = g0; d_g1[t] = g1;
        d_r1[t] = prob < (g1 / 0.2f);
    }
    __syncthreads();
    if (threadIdx.x < Ee) atomicAdd(&d_gsum[b*Ee + threadIdx.x], s_g[threadIdx.x]);
    if (threadIdx.x == 0) atomicAdd(&d_zsum, s_z);
}

// =====================  capacity scan (smem-staged)  ======================
__global__ void __launch_bounds__(256) scan_kernel() {
    int b = blockIdx.x;
    __shared__ int se0[Nn];
    __shared__ int se1[Nn];     // expert for k=1 or -1
    for (int i = threadIdx.x; i < Nn; i += 256) {
        int t = b*Nn + i;
        se0[i] = d_e0[t];
        se1[i] = d_r1[t] ? d_e1[t] : -1;
    }
    __syncthreads();
    if (threadIdx.x >= 32) return;

    int lane = threadIdx.x;
    unsigned ltmask = (1u << lane) - 1u;

    int cnt[Ee];
#pragma unroll
    for (int e = 0; e < Ee; e++) cnt[e] = 0;

    for (int c = 0; c < Nn/32; c++) {
        int n = c*32 + lane;
        int t = b*Nn + n;
        int e = se0[n];
        int pos = 0;
#pragma unroll
        for (int ei = 0; ei < Ee; ei++) {
            unsigned bal = __ballot_sync(0xffffffffu, e == ei);
            if (e == ei) pos = cnt[ei] + __popc(bal & ltmask);
            cnt[ei] += __popc(bal);
        }
        if (pos < CAP) {
            int slot = (b*Ee + e)*RPG + pos;
            d_slot_tok[slot] = n;
            d_s0[t] = slot;
        } else {
            d_s0[t] = -1;
        }
    }
    int c0[Ee];
#pragma unroll
    for (int e = 0; e < Ee; e++) c0[e] = min(cnt[e], CAP);
    if (lane < Ee) d_c0cnt[b*Ee + lane] = c0[lane];

    int cnt1[Ee];
#pragma unroll
    for (int e = 0; e < Ee; e++) cnt1[e] = 0;
    for (int c = 0; c < Nn/32; c++) {
        int n = c*32 + lane;
        int t = b*Nn + n;
        int e = se1[n];
        int posl = 0;
#pragma unroll
        for (int ei = 0; ei < Ee; ei++) {
            unsigned bal = __ballot_sync(0xffffffffu, e == ei);
            if (e == ei) posl = cnt1[ei] + __popc(bal & ltmask);
            cnt1[ei] += __popc(bal);
        }
        if (e >= 0) {
            int pos = c0[e] + posl;
            if (pos < CAP) {
                int slot = (b*Ee + e)*RPG + pos;
                d_slot_tok[slot] = n;
                d_s1[t] = slot;
            } else {
                d_s1[t] = -1;
            }
        } else {
            d_s1[t] = -1;
        }
    }
}

// =====================  weight conversion  ======================
// w1: [e][k=512][2730] fp32 -> d_w1bf [e][c=2816][k=512] bf16,
// col c<2730 maps to src col (c&1)*1365 + (c>>1)  (u/g interleave)
__global__ void convw1_kernel(const float* __restrict__ w1) {
    __shared__ float t[32][33];
    int e = blockIdx.z, k0 = blockIdx.y*32, c0 = blockIdx.x*32;
    int tx = threadIdx.x & 31, ty = threadIdx.x >> 5;   // 256 thr = 32x8
#pragma unroll
    for (int i = 0; i < 4; i++) {
        int k = k0 + ty + i*8, c = c0 + tx;
        float v = 0.f;
        if (c < H2) {
            int m = (c & 1)*Hh + (c >> 1);
            v = w1[((size_t)e*Dd + k)*H2 + m];
        }
        t[ty + i*8][tx] = v;
    }
    __syncthreads();
#pragma unroll
    for (int i = 0; i < 4; i++) {
        int c = c0 + ty + i*8, k = k0 + tx;
        d_w1bf[((size_t)e*NP1 + c)*Dd + k] = __float2bfloat16(t[tx][ty + i*8]);
    }
}
// w2: [e][k=1365][512] fp32 -> d_w2bf [e][n=512][k=1408] bf16 (k pad zero)
__global__ void convw2_kernel(const float* __restrict__ w2) {
    __shared__ float t[32][33];
    int e = blockIdx.z, k0 = blockIdx.y*32, n0 = blockIdx.x*32;
    int tx = threadIdx.x & 31, ty = threadIdx.x >> 5;
#pragma unroll
    for (int i = 0; i < 4; i++) {
        int k = k0 + ty + i*8, n = n0 + tx;
        float v = 0.f;
        if (k < Hh) v = w2[((size_t)e*Hh + k)*Dd + n];
        t[ty + i*8][tx] = v;
    }
    __syncthreads();
#pragma unroll
    for (int i = 0; i < 4; i++) {
        int n = n0 + ty + i*8, k = k0 + tx;
        d_w2bf[((size_t)e*Dd + n)*KP2 + k] = __float2bfloat16(t[tx][ty + i*8]);
    }
}

// =====================  gather xg rows into slot layout (bf16) ===============
__global__ void gather_kernel() {
    int r = blockIdx.x;
    int tid = threadIdx.x;   // 128
    int tok = d_slot_tok[r];
    int b = r / (Ee*RPG);
    int d0 = tid * 4;
    float4 v = make_float4(0.f, 0.f, 0.f, 0.f);
    if (tok >= 0)
        v = *(const float4*)(d_xg + ((size_t)(b*Nn + tok))*Dd + d0);
    __nv_bfloat162 lo = __floats2bfloat162_rn(v.x, v.y);
    __nv_bfloat162 hi = __floats2bfloat162_rn(v.z, v.w);
    *(__nv_bfloat162*)(d_einbf + (size_t)r*Dd + d0)     = lo;
    *(__nv_bfloat162*)(d_einbf + (size_t)r*Dd + d0 + 2) = hi;
}

// =====================  HMMA mainloop (MTx128x32 tile, 3-stage, 1 sync/iter) =
// warp grid 2(M) x 4(N); per-warp (MT/2)x32; accum acc[MT/32][4][4]
template<int KT, int MT>
__device__ __forceinline__ void run_gemm(
        const __nv_bfloat16* __restrict__ Ag, int ldA,
        const __nv_bfloat16* __restrict__ Bg, int ldB,
        uint32_t sA, uint32_t sB, float (*acc)[4][4], int tid)
{
    int lane = tid & 31, w = tid >> 5;
    int wm = w & 1, wn = w >> 1;
    int rA = wm*(MT/2) + (lane & 15);
    int cA = lane >> 4;
    int rB = wn*32 + (lane & 7) + ((lane >> 4) << 3);
    int cB = (lane >> 3) & 1;

#define LOAD_STAGE(s, kt) {                                              \
        uint32_t dA = sA + (s)*8192, dB = sB + (s)*8192;                 \
        const __nv_bfloat16* Akt = Ag + (kt)*32;                         \
        const __nv_bfloat16* Bkt = Bg + (kt)*32;                         \
        _Pragma("unroll")                                                \
        for (int i = 0; i < MT/64; i++) {                                \
            int idx = i*256 + tid;                                       \
            int r = idx >> 2, c = idx & 3;                               \
            cpasync16(dA + swz(r, c), Akt + (size_t)r*ldA + c*8);        \
        }                                                                \
        _Pragma("unroll")                                                \
        for (int i = 0; i < 2; i++) {                                    \
            int idx = i*256 + tid;                                       \
            int r = idx >> 2, c = idx & 3;                               \
            cpasync16(dB + swz(r, c), Bkt + (size_t)r*ldB + c*8);        \
        }                                                                \
    }

    LOAD_STAGE(0, 0); CP_COMMIT();
    LOAD_STAGE(1, 1); CP_COMMIT();

#pragma unroll 1
    for (int kt = 0; kt < KT; kt++) {
        CP_WAIT1();              // group kt complete
        __syncthreads();         // all warps done reading buffer (kt+2)%3
        if (kt + 2 < KT) LOAD_STAGE((kt + 2) % 3, kt + 2);
        CP_COMMIT();             // commit every iter (uniform group counts)

        int st = kt % 3;
        uint32_t aA = sA + st*8192, aB = sB + st*8192;
#pragma unroll
        for (int ks = 0; ks < 2; ks++) {
            uint32_t a[MT/32][4], b[2][4];
#pragma unroll
            for (int mi = 0; mi < MT/32; mi++)
                ldsm4(a[mi], aA + swz(rA + mi*16, ks*2 + cA));
#pragma unroll
            for (int nj = 0; nj < 2; nj++)
                ldsm4(b[nj], aB + swz(rB + nj*16, ks*2 + cB));
#pragma unroll
            for (int mi = 0; mi < MT/32; mi++)
#pragma unroll
                for (int n8 = 0; n8 < 4; n8++)
                    mma16816(acc[mi][n8], a[mi],
                             b[n8 >> 1][(n8 & 1)*2], b[n8 >> 1][(n8 & 1)*2 + 1]);
        }
    }
#undef LOAD_STAGE
}

// =====================  GEMM1 (HMMA) + GEGLU epilogue ======================
template<int MT>
__global__ void __launch_bounds__(256, 2) gemm1_mma(const float* __restrict__ b1,
                                                    const float* __restrict__ mb) {
    __shared__ __align__(1024) char sAbuf[3][8192];
    __shared__ __align__(1024) char sBbuf[3][8192];
    int tid = threadIdx.x;
    int grp = blockIdx.z, e = grp & 7, nt = blockIdx.x;
    int mtOff = (MT == 128) ? blockIdx.y*128 : 256;
    const __nv_bfloat16* Ag = d_einbf + (size_t)(grp*RPG + mtOff)*Dd;
    const __nv_bfloat16* Bg = d_w1bf + ((size_t)e*NP1 + nt*128)*Dd;

    float acc[MT/32][4][4] = {};
    run_gemm<16, MT>(Ag, Dd, Bg, Dd, smem_u32(sAbuf), smem_u32(sBbuf), acc, tid);

    int lane = tid & 31, w = tid >> 5;
    int wm = w & 1, wn = w >> 1;
    int g = lane >> 2, tc = lane & 3;
    int rowbase = grp*RPG + mtOff + wm*(MT/2);
    int ncolbase = nt*128 + wn*32;
#pragma unroll
    for (int n8 = 0; n8 < 4; n8++) {
        int j = (ncolbase + n8*8 + tc*2) >> 1;
        float b1u = 0.f, b1g = 0.f, mbv = 0.f;
        if (j < Hh) {
            b1u = b1[e*H2 + j];
            b1g = b1[e*H2 + Hh + j];
            mbv = mb[e*Hh + j];
        }
#pragma unroll
        for (int mi = 0; mi < MT/32; mi++)
#pragma unroll
            for (int half = 0; half < 2; half++) {
                int row = rowbase + mi*16 + g + half*8;
                float av = 0.f;
                if (j < Hh) {
                    float u  = acc[mi][n8][half*2 + 0] + b1u;
                    float gg = acc[mi][n8][half*2 + 1] + b1g;
                    float gel = 0.5f * gg * (1.f + erff(gg * 0.70710678118654752440f));
                    av = u * gel * mbv;
                }
                d_actbf[(size_t)row*KP2 + j] = __float2bfloat16(av);
            }
    }
}

// =====================  GEMM2 (HMMA) + bias epilogue ======================
template<int MT>
__global__ void __launch_bounds__(256, 2) gemm2_mma(const float* __restrict__ b2) {
    __shared__ __align__(1024) char sAbuf[3][8192];
    __shared__ __align__(1024) char sBbuf[3][8192];
    int tid = threadIdx.x;
    int grp = blockIdx.z, e = grp & 7, nt = blockIdx.x;
    int mtOff = (MT == 128) ? blockIdx.y*128 : 256;
    const __nv_bfloat16* Ag = d_actbf + (size_t)(grp*RPG + mtOff)*KP2;
    const __nv_bfloat16* Bg = d_w2bf + ((size_t)e*Dd + nt*128)*KP2;

    float acc[MT/32][4][4] = {};
    run_gemm<44, MT>(Ag, KP2, Bg, KP2, smem_u32(sAbuf), smem_u32(sBbuf), acc, tid);

    int lane = tid & 31, w = tid >> 5;
    int wm = w & 1, wn = w >> 1;
    int g = lane >> 2, tc = lane & 3;
    int rowbase = grp*RPG + mtOff + wm*(MT/2);
    int ncolbase = nt*128 + wn*32;
#pragma unroll
    for (int n8 = 0; n8 < 4; n8++) {
        int ncol = ncolbase + n8*8 + tc*2;
        float bz0 = b2[e*Dd + ncol];
        float bz1 = b2[e*Dd + ncol + 1];
#pragma unroll
        for (int mi = 0; mi < MT/32; mi++)
#pragma unroll
            for (int half = 0; half < 2; half++) {
                int row = rowbase + mi*16 + g + half*8;
                float2 v;
                v.x = acc[mi][n8][half*2 + 0] + bz0;
                v.y = acc[mi][n8][half*2 + 1] + bz1;
                *(float2*)(d_eo + (size_t)row*Dd + ncol) = v;
            }
    }
}

// =====================  combine + residual + LayerNorm ======================
__global__ void final_kernel(const float* __restrict__ x,
                             const float* __restrict__ lng,
                             const float* __restrict__ lnb,
                             float* __restrict__ out) {
    int t = blockIdx.x;
    int tid = threadIdx.x;   // 128
    int s0 = d_s0[t], s1 = d_s1[t];
    float g0 = d_g0[t], g1 = d_g1[t];
    float y[4];
#pragma unroll
    for (int i = 0; i < 4; i++) {
        int d = tid + i*128;
        float acc = x[(size_t)t*Dd + d];
        if (s0 >= 0) acc += g0 * d_eo[(size_t)s0*Dd + d];
        if (s1 >= 0) acc += g1 * d_eo[(size_t)s1*Dd + d];
        y[i] = acc;
    }
    __shared__ float s_red[128];
    float s = y[0] + y[1] + y[2] + y[3];
    s_red[tid] = s;
    __syncthreads();
    for (int st = 64; st > 0; st >>= 1) {
        if (tid < st) s_red[tid] += s_red[tid + st];
        __syncthreads();
    }
    float mu = s_red[0] / (float)Dd;
    __syncthreads();
    float sv = 0.f;
#pragma unroll
    for (int i = 0; i < 4; i++) { float dv = y[i] - mu; sv += dv * dv; }
    s_red[tid] = sv;
    __syncthreads();
    for (int st = 64; st > 0; st >>= 1) {
        if (tid < st) s_red[tid] += s_red[tid + st];
        __syncthreads();
    }
    float var = s_red[0] / (float)Dd;
    float rstd = rsqrtf(var + 1e-5f);
#pragma unroll
    for (int i = 0; i < 4; i++) {
        int d = tid + i*128;
        out[(size_t)t*Dd + d] = (y[i] - mu) * rstd * lng[d] + lnb[d];
    }
}

// =====================  aux-loss scalar ======================
__global__ void aux_kernel(float* __restrict__ out, int out_size) {
    int tid = threadIdx.x;   // 32
    float v = (d_gsum[tid] / (float)Nn) * ((float)d_c0cnt[tid] / (float)Nn);
#pragma unroll
    for (int o = 16; o > 0; o >>= 1) v += __shfl_down_sync(0xffffffffu, v, o);
    if (tid == 0) {
        float bal = (v / (float)(Bb*Ee)) * (float)(Ee*Ee);
        float rz = d_zsum / (float)NTOK;
        float aux = 0.01f * bal + 0.001f * rz;
        for (int i = BND; i < out_size; i++) out[i] = aux;
    }
}

// =====================  launch ======================
extern "C" void kernel_launch(void* const* d_in, const int* in_sizes, int n_in,
                              void* d_out, int out_size) {
    const float* x   = (const float*)d_in[0];
    const float* gw  = (const float*)d_in[1];
    const float* pg  = (const float*)d_in[2];
    const float* w1  = (const float*)d_in[3];
    const float* b1  = (const float*)d_in[4];
    const float* mb  = (const float*)d_in[5];
    const float* w2  = (const float*)d_in[6];
    const float* b2  = (const float*)d_in[7];
    const float* lng = (const float*)d_in[8];
    const float* lnb = (const float*)d_in[9];
    float* out = (float*)d_out;

    init_kernel<<<(ROWS + 255)/256, 256>>>();
    token_kernel<<<NTOK/8, 256>>>(x, gw, pg);
    scan_kernel<<<Bb, 256>>>();
    convw1_kernel<<<dim3(NP1/32, Dd/32, Ee), 256>>>(w1);
    convw2_kernel<<<dim3(Dd/32, KP2/32, Ee), 256>>>(w2);
    gather_kernel<<<ROWS, 128>>>();
    gemm1_mma<128><<<dim3(NP1/128, 2, NGRP), 256>>>(b1, mb);
    gemm1_mma<64><<<dim3(NP1/128, 1, NGRP), 256>>>(b1, mb);
    gemm2_mma<128><<<dim3(Dd/128, 2, NGRP), 256>>>(b2);
    gemm2_mma<64><<<dim3(Dd/128, 1, NGRP), 256>>>(b2);
    final_kernel<<<NTOK, 128>>>(x, lng, lnb, out);
    aux_kernel<<<1, 32>>>(out, out_size);
}